// round 11
// baseline (speedup 1.0000x reference)
#include <cuda_runtime.h>

#define DIM    256    // DIM_IN
#define BATCH  1024   // B
#define NI     32640  // C(256,2)

#define TT     32     // i/j tile size (8 tiles of 32)
#define ROWS   64     // batch rows per item
#define ITEMS  2      // y-items per block (pipelined)
#define NPAIR  36     // unordered tile pairs
#define NYB    (BATCH / (ROWS * ITEMS))   // 8 y-slices of 128 rows
#define XP     36     // x tile pitch in floats
#define SROWS  (ROWS * ITEMS)             // 128 rows per y-slice

__constant__ unsigned char cTI[NPAIR] = {0,0,0,0,0,0,0,0, 1,1,1,1,1,1,1, 2,2,2,2,2,2,
                                         3,3,3,3,3, 4,4,4,4, 5,5,5, 6,6, 7};
__constant__ unsigned char cTJ[NPAIR] = {0,1,2,3,4,5,6,7, 1,2,3,4,5,6,7, 2,3,4,5,6,7,
                                         3,4,5,6,7, 4,5,6,7, 5,6,7, 6,7, 7};

// scratch[row][pair]: per-pair row partials. 1024*36*4B = 144KB.
// Fully rewritten every run -> needs no init. 144B rows: 9 aligned float4s.
__device__ __align__(16) float g_scratch[BATCH * NPAIR];
__device__ int g_cnt[NYB];   // zero at module load; reset by last block per run

// Packed f32x2 FMA
__device__ __forceinline__ float2 fma2(float2 a, float2 b, float2 c) {
    float2 d;
    asm("fma.rn.f32x2 %0, %1, %2, %3;"
        : "=l"(*reinterpret_cast<unsigned long long*>(&d))
        : "l"(*reinterpret_cast<const unsigned long long*>(&a)),
          "l"(*reinterpret_cast<const unsigned long long*>(&b)),
          "l"(*reinterpret_cast<const unsigned long long*>(&c)));
    return d;
}

// 16B global->shared async copy (LDGSTS)
__device__ __forceinline__ void cp_async16(unsigned smem_addr, const void* gptr) {
    asm volatile("cp.async.ca.shared.global [%0], [%1], 16;"
                 :: "r"(smem_addr), "l"(__cvta_generic_to_global(gptr)) : "memory");
}

// out[b] = sum_{i<j} (w0+w1)*w0*w1 * x[b,i]*x[b,j]
// R8's measured-best compute (2-item cp.async pipeline, shared A tile,
// 2 rows x 4 j threads) + single launch + scratch/last-block-gather output.
__global__ void __launch_bounds__(256, 2)
quad_kernel(const float* __restrict__ x, const float* __restrict__ w,
            float* __restrict__ out) {
    __shared__ __align__(16) float As[TT * TT];                 // 4KB
    __shared__ __align__(16) float xIb[ITEMS][ROWS * XP];       // 2 x 9.2KB
    __shared__ __align__(16) float xJb[ITEMS][ROWS * XP];       // 2 x 9.2KB
    __shared__ int sIsLast;

    const int t     = threadIdx.x;
    const int pair  = blockIdx.x;
    const int yb    = blockIdx.y;
    const int ibase = cTI[pair] * TT;
    const int jbase = cTJ[pair] * TT;
    const int rbase = yb * SROWS;

    // ---- Issue BOTH items' x tiles as cp.async groups (one group per item).
#pragma unroll
    for (int item = 0; item < ITEMS; ++item) {
        const unsigned sI = (unsigned)__cvta_generic_to_shared(xIb[item]);
        const unsigned sJ = (unsigned)__cvta_generic_to_shared(xJb[item]);
        const int rb = rbase + item * ROWS;
#pragma unroll
        for (int s = 0; s < 2; ++s) {
            const int c  = s * 256 + t;
            const int r  = c >> 3, cc = c & 7;       // 64 rows x 8 16B-chunks
            const long rowoff = (long)(rb + r) * DIM;
            cp_async16(sI + (r * XP + cc * 4) * 4, x + rowoff + ibase + cc * 4);
            cp_async16(sJ + (r * XP + cc * 4) * 4, x + rowoff + jbase + cc * 4);
        }
        asm volatile("cp.async.commit_group;" ::: "memory");
    }

    // ---- A tile (shared by both items): batched coalesced w loads, then STS.
    float w0v[4], w1v[4];
    bool  val[4];
#pragma unroll
    for (int s = 0; s < 4; ++s) {
        const int idx = s * 256 + t;
        const int gi = ibase + (idx >> 5);
        const int gj = jbase + (idx & 31);
        val[s] = (gj > gi);
        const int k = val[s] ? (gi * 255 - (gi * (gi - 1)) / 2 + (gj - gi - 1)) : 0;
        w0v[s] = __ldg(&w[k]);
        w1v[s] = __ldg(&w[NI + k]);
    }
#pragma unroll
    for (int s = 0; s < 4; ++s) {
        const int idx = s * 256 + t;
        As[idx] = val[s] ? (w0v[s] + w1v[s]) * w0v[s] * w1v[s] : 0.0f;
    }

    // ---- Thread tile: 2 rows x 4 j (lanes = j-pairs).
    const int jg = t & 7;
    const int j0 = jg * 4;
    const int r0 = (t >> 3) * 2;

#pragma unroll
    for (int item = 0; item < ITEMS; ++item) {
        if (item == 0) { asm volatile("cp.async.wait_group 1;" ::: "memory"); }
        else           { asm volatile("cp.async.wait_group 0;" ::: "memory"); }
        __syncthreads();

        const float* xIs = xIb[item];
        const float* xJs = xJb[item];

        float2 a00 = {0.f,0.f}, a01 = {0.f,0.f}, a10 = {0.f,0.f}, a11 = {0.f,0.f};
#pragma unroll
        for (int i = 0; i < TT; ++i) {
            const float xv0 = xIs[ r0      * XP + i];
            const float xv1 = xIs[(r0 + 1) * XP + i];
            const float4 av = *reinterpret_cast<const float4*>(&As[i * TT + j0]);
            const float2 A01 = make_float2(av.x, av.y);
            const float2 A23 = make_float2(av.z, av.w);
            a00 = fma2(make_float2(xv0, xv0), A01, a00);
            a01 = fma2(make_float2(xv0, xv0), A23, a01);
            a10 = fma2(make_float2(xv1, xv1), A01, a10);
            a11 = fma2(make_float2(xv1, xv1), A23, a11);
        }

        const float4 xj0 = *reinterpret_cast<const float4*>(&xJs[ r0      * XP + j0]);
        const float4 xj1 = *reinterpret_cast<const float4*>(&xJs[(r0 + 1) * XP + j0]);
        float2 s0 = fma2(a00, make_float2(xj0.x, xj0.y),
                    fma2(a01, make_float2(xj0.z, xj0.w), make_float2(0.f, 0.f)));
        float2 s1 = fma2(a10, make_float2(xj1.x, xj1.y),
                    fma2(a11, make_float2(xj1.z, xj1.w), make_float2(0.f, 0.f)));
        float v0 = s0.x + s0.y;
        float v1 = s1.x + s1.y;

#pragma unroll
        for (int m = 4; m > 0; m >>= 1) {
            v0 += __shfl_xor_sync(0xffffffffu, v0, m, 32);
            v1 += __shfl_xor_sync(0xffffffffu, v1, m, 32);
        }
        if (jg == 0) {   // plain STG to scratch: no atomics, no init dependency
            const int rb = rbase + item * ROWS;
            g_scratch[(rb + r0)     * NPAIR + pair] = v0;
            g_scratch[(rb + r0 + 1) * NPAIR + pair] = v1;
        }
    }

    // ---- Decoupled completion: 36th-arriving block per y-slice gathers -> out.
    __threadfence();
    __syncthreads();
    if (t == 0) sIsLast = (atomicAdd(&g_cnt[yb], 1) == NPAIR - 1);
    __syncthreads();
    if (sIsLast) {
        __threadfence();   // acquire: all pairs' scratch stores visible
        if (t < SROWS) {
            const float4* row = reinterpret_cast<const float4*>(
                &g_scratch[(rbase + t) * NPAIR]);   // 36 floats = 9 float4, 16B aligned
            float tot = 0.0f;
#pragma unroll
            for (int q4 = 0; q4 < NPAIR / 4; ++q4) {
                const float4 v = row[q4];           // 9 independent LDG.128 (MLP 9)
                tot += (v.x + v.y) + (v.z + v.w);
            }
            out[rbase + t] = tot;
        }
        __syncthreads();
        if (t == 0) atomicExch(&g_cnt[yb], 0);      // replay-safe reset
    }
}

extern "C" void kernel_launch(void* const* d_in, const int* in_sizes, int n_in,
                              void* d_out, int out_size) {
    const float* x = (const float*)d_in[0];
    const float* w = (const float*)d_in[1];
    float* out = (float*)d_out;

    quad_kernel<<<dim3(NPAIR, NYB), 256>>>(x, w, out);   // ONE launch, 288 blocks
}

// round 12
// speedup vs baseline: 1.0052x; 1.0052x over previous
#include <cuda_runtime.h>

#define DIM    256    // DIM_IN
#define BATCH  1024   // B
#define NI     32640  // C(256,2)

#define TT     32     // i/j tile size (8 tiles of 32)
#define ROWS   64     // batch rows per item
#define ITEMS  2      // y-items per block (pipelined)
#define NPAIR  36     // unordered tile pairs
#define NYB    (BATCH / (ROWS * ITEMS))   // 8 y-slices of 128 rows
#define SROWS  (ROWS * ITEMS)             // 128 rows per y-slice
#define XP     36     // x tile pitch in floats

__constant__ unsigned char cTI[NPAIR] = {0,0,0,0,0,0,0,0, 1,1,1,1,1,1,1, 2,2,2,2,2,2,
                                         3,3,3,3,3, 4,4,4,4, 5,5,5, 6,6, 7};
__constant__ unsigned char cTJ[NPAIR] = {0,1,2,3,4,5,6,7, 1,2,3,4,5,6,7, 2,3,4,5,6,7,
                                         3,4,5,6,7, 4,5,6,7, 5,6,7, 6,7, 7};

// Persistent accumulator, ZERO at module load. Invariant: zero at kernel entry;
// restored to zero by each y-slice's last block after it copies to out.
__device__ float g_accum[BATCH];
__device__ int   g_cnt[NYB];   // same invariant (reset by last block per slice)

// Packed f32x2 FMA
__device__ __forceinline__ float2 fma2(float2 a, float2 b, float2 c) {
    float2 d;
    asm("fma.rn.f32x2 %0, %1, %2, %3;"
        : "=l"(*reinterpret_cast<unsigned long long*>(&d))
        : "l"(*reinterpret_cast<const unsigned long long*>(&a)),
          "l"(*reinterpret_cast<const unsigned long long*>(&b)),
          "l"(*reinterpret_cast<const unsigned long long*>(&c)));
    return d;
}

// 16B global->shared async copy (LDGSTS)
__device__ __forceinline__ void cp_async16(unsigned smem_addr, const void* gptr) {
    asm volatile("cp.async.ca.shared.global [%0], [%1], 16;"
                 :: "r"(smem_addr), "l"(__cvta_generic_to_global(gptr)) : "memory");
}

// L2-coherent load (bypass L1: atomics land in L2, L2 is authoritative)
__device__ __forceinline__ float ldcg(const float* p) {
    float v;
    asm volatile("ld.global.cg.f32 %0, [%1];" : "=f"(v) : "l"(p));
    return v;
}

// out[b] = sum_{i<j} (w0+w1)*w0*w1 * x[b,i]*x[b,j]
// R8's compute verbatim; atomics target persistent g_accum (pre-zeroed,
// no init pass); 36th-arriving block per y-slice copies accum -> out and
// restores the zero invariant. ONE launch, no spins, minimal fences.
__global__ void __launch_bounds__(256, 2)
quad_kernel(const float* __restrict__ x, const float* __restrict__ w,
            float* __restrict__ out) {
    __shared__ __align__(16) float As[TT * TT];                 // 4KB
    __shared__ __align__(16) float xIb[ITEMS][ROWS * XP];       // 2 x 9.2KB
    __shared__ __align__(16) float xJb[ITEMS][ROWS * XP];       // 2 x 9.2KB
    __shared__ int sIsLast;

    const int t     = threadIdx.x;
    const int pair  = blockIdx.x;
    const int yb    = blockIdx.y;
    const int ibase = cTI[pair] * TT;
    const int jbase = cTJ[pair] * TT;
    const int rbase = yb * SROWS;

    // ---- Issue BOTH items' x tiles as cp.async groups (one group per item).
#pragma unroll
    for (int item = 0; item < ITEMS; ++item) {
        const unsigned sI = (unsigned)__cvta_generic_to_shared(xIb[item]);
        const unsigned sJ = (unsigned)__cvta_generic_to_shared(xJb[item]);
        const int rb = rbase + item * ROWS;
#pragma unroll
        for (int s = 0; s < 2; ++s) {
            const int c  = s * 256 + t;
            const int r  = c >> 3, cc = c & 7;       // 64 rows x 8 16B-chunks
            const long rowoff = (long)(rb + r) * DIM;
            cp_async16(sI + (r * XP + cc * 4) * 4, x + rowoff + ibase + cc * 4);
            cp_async16(sJ + (r * XP + cc * 4) * 4, x + rowoff + jbase + cc * 4);
        }
        asm volatile("cp.async.commit_group;" ::: "memory");
    }

    // ---- A tile (shared by both items): batched coalesced w loads, then STS.
    float w0v[4], w1v[4];
    bool  val[4];
#pragma unroll
    for (int s = 0; s < 4; ++s) {
        const int idx = s * 256 + t;
        const int gi = ibase + (idx >> 5);
        const int gj = jbase + (idx & 31);
        val[s] = (gj > gi);
        const int k = val[s] ? (gi * 255 - (gi * (gi - 1)) / 2 + (gj - gi - 1)) : 0;
        w0v[s] = __ldg(&w[k]);
        w1v[s] = __ldg(&w[NI + k]);
    }
#pragma unroll
    for (int s = 0; s < 4; ++s) {
        const int idx = s * 256 + t;
        As[idx] = val[s] ? (w0v[s] + w1v[s]) * w0v[s] * w1v[s] : 0.0f;
    }

    // ---- Thread tile: 2 rows x 4 j (lanes = j-pairs).
    const int jg = t & 7;
    const int j0 = jg * 4;
    const int r0 = (t >> 3) * 2;

#pragma unroll
    for (int item = 0; item < ITEMS; ++item) {
        if (item == 0) { asm volatile("cp.async.wait_group 1;" ::: "memory"); }
        else           { asm volatile("cp.async.wait_group 0;" ::: "memory"); }
        __syncthreads();

        const float* xIs = xIb[item];
        const float* xJs = xJb[item];

        float2 a00 = {0.f,0.f}, a01 = {0.f,0.f}, a10 = {0.f,0.f}, a11 = {0.f,0.f};
#pragma unroll
        for (int i = 0; i < TT; ++i) {
            const float xv0 = xIs[ r0      * XP + i];
            const float xv1 = xIs[(r0 + 1) * XP + i];
            const float4 av = *reinterpret_cast<const float4*>(&As[i * TT + j0]);
            const float2 A01 = make_float2(av.x, av.y);
            const float2 A23 = make_float2(av.z, av.w);
            a00 = fma2(make_float2(xv0, xv0), A01, a00);
            a01 = fma2(make_float2(xv0, xv0), A23, a01);
            a10 = fma2(make_float2(xv1, xv1), A01, a10);
            a11 = fma2(make_float2(xv1, xv1), A23, a11);
        }

        const float4 xj0 = *reinterpret_cast<const float4*>(&xJs[ r0      * XP + j0]);
        const float4 xj1 = *reinterpret_cast<const float4*>(&xJs[(r0 + 1) * XP + j0]);
        float2 s0 = fma2(a00, make_float2(xj0.x, xj0.y),
                    fma2(a01, make_float2(xj0.z, xj0.w), make_float2(0.f, 0.f)));
        float2 s1 = fma2(a10, make_float2(xj1.x, xj1.y),
                    fma2(a11, make_float2(xj1.z, xj1.w), make_float2(0.f, 0.f)));
        float v0 = s0.x + s0.y;
        float v1 = s1.x + s1.y;

#pragma unroll
        for (int m = 4; m > 0; m >>= 1) {
            v0 += __shfl_xor_sync(0xffffffffu, v0, m, 32);
            v1 += __shfl_xor_sync(0xffffffffu, v1, m, 32);
        }
        if (jg == 0) {   // accumulate into pre-zeroed persistent buffer
            const int rb = rbase + item * ROWS;
            atomicAdd(&g_accum[rb + r0],     v0);
            atomicAdd(&g_accum[rb + r0 + 1], v1);
        }
    }

    // ---- Minimal decoupled completion.
    __threadfence();                 // order this block's atomics before the count
    __syncthreads();
    if (t == 0) sIsLast = (atomicAdd(&g_cnt[yb], 1) == NPAIR - 1);
    __syncthreads();
    if (sIsLast) {
        __threadfence();             // acquire side
        if (t < SROWS) {
            const int b = rbase + t;
            out[b] = ldcg(&g_accum[b]);  // L2-coherent read (atomics live in L2)
            g_accum[b] = 0.0f;           // restore zero invariant for next replay
        }
        if (t == 0) atomicExch(&g_cnt[yb], 0);   // restore counter invariant
    }
}

extern "C" void kernel_launch(void* const* d_in, const int* in_sizes, int n_in,
                              void* d_out, int out_size) {
    const float* x = (const float*)d_in[0];
    const float* w = (const float*)d_in[1];
    float* out = (float*)d_out;

    quad_kernel<<<dim3(NPAIR, NYB), 256>>>(x, w, out);   // ONE launch, 288 blocks
}

// round 13
// speedup vs baseline: 1.1950x; 1.1889x over previous
#include <cuda_runtime.h>

#define DIM    256    // DIM_IN
#define BATCH  1024   // B
#define NI     32640  // C(256,2)

#define TT     32     // i/j tile size (8 tiles of 32)
#define ROWS   64     // batch rows per item
#define ITEMS  2      // y-items per block (pipelined)
#define NPAIR  36     // unordered tile pairs
#define XP     36     // x tile pitch in floats

__constant__ unsigned char cTI[NPAIR] = {0,0,0,0,0,0,0,0, 1,1,1,1,1,1,1, 2,2,2,2,2,2,
                                         3,3,3,3,3, 4,4,4,4, 5,5,5, 6,6, 7};
__constant__ unsigned char cTJ[NPAIR] = {0,1,2,3,4,5,6,7, 1,2,3,4,5,6,7, 2,3,4,5,6,7,
                                         3,4,5,6,7, 4,5,6,7, 5,6,7, 6,7, 7};

__global__ void zero_out_kernel(float* __restrict__ out) {
    out[blockIdx.x * 256 + threadIdx.x] = 0.0f;   // 4 blocks x 256
}

// Packed f32x2 FMA
__device__ __forceinline__ float2 fma2(float2 a, float2 b, float2 c) {
    float2 d;
    asm("fma.rn.f32x2 %0, %1, %2, %3;"
        : "=l"(*reinterpret_cast<unsigned long long*>(&d))
        : "l"(*reinterpret_cast<const unsigned long long*>(&a)),
          "l"(*reinterpret_cast<const unsigned long long*>(&b)),
          "l"(*reinterpret_cast<const unsigned long long*>(&c)));
    return d;
}

// 16B global->shared async copy (LDGSTS)
__device__ __forceinline__ void cp_async16(unsigned smem_addr, const void* gptr) {
    asm volatile("cp.async.ca.shared.global [%0], [%1], 16;"
                 :: "r"(smem_addr), "l"(__cvta_generic_to_global(gptr)) : "memory");
}

// out[b] = sum_{i<j} (w0+w1)*w0*w1 * x[b,i]*x[b,j]
// R8's measured-best structure (2-item cp.async pipeline, shared A tile,
// 2 rows x 4 j threads, atomics into zeroed out) + depth-1 software prefetch
// of the mainloop LDS so FFMA2s overlap the next iteration's LDS latency.
__global__ void __launch_bounds__(256, 2)
quad_kernel(const float* __restrict__ x, const float* __restrict__ w,
            float* __restrict__ out) {
    __shared__ __align__(16) float As[TT * TT];                 // 4KB
    __shared__ __align__(16) float xIb[ITEMS][ROWS * XP];       // 2 x 9.2KB
    __shared__ __align__(16) float xJb[ITEMS][ROWS * XP];       // 2 x 9.2KB

    const int t     = threadIdx.x;
    const int pair  = blockIdx.x;
    const int ibase = cTI[pair] * TT;
    const int jbase = cTJ[pair] * TT;
    const int rbase = blockIdx.y * (ROWS * ITEMS);

    // ---- Issue BOTH items' x tiles as cp.async groups (one group per item).
#pragma unroll
    for (int item = 0; item < ITEMS; ++item) {
        const unsigned sI = (unsigned)__cvta_generic_to_shared(xIb[item]);
        const unsigned sJ = (unsigned)__cvta_generic_to_shared(xJb[item]);
        const int rb = rbase + item * ROWS;
#pragma unroll
        for (int s = 0; s < 2; ++s) {
            const int c  = s * 256 + t;
            const int r  = c >> 3, cc = c & 7;       // 64 rows x 8 16B-chunks
            const long rowoff = (long)(rb + r) * DIM;
            cp_async16(sI + (r * XP + cc * 4) * 4, x + rowoff + ibase + cc * 4);
            cp_async16(sJ + (r * XP + cc * 4) * 4, x + rowoff + jbase + cc * 4);
        }
        asm volatile("cp.async.commit_group;" ::: "memory");
    }

    // ---- A tile (shared by both items): batched coalesced w loads, then STS.
    float w0v[4], w1v[4];
    bool  val[4];
#pragma unroll
    for (int s = 0; s < 4; ++s) {
        const int idx = s * 256 + t;
        const int gi = ibase + (idx >> 5);
        const int gj = jbase + (idx & 31);
        val[s] = (gj > gi);
        const int k = val[s] ? (gi * 255 - (gi * (gi - 1)) / 2 + (gj - gi - 1)) : 0;
        w0v[s] = __ldg(&w[k]);
        w1v[s] = __ldg(&w[NI + k]);
    }
#pragma unroll
    for (int s = 0; s < 4; ++s) {
        const int idx = s * 256 + t;
        As[idx] = val[s] ? (w0v[s] + w1v[s]) * w0v[s] * w1v[s] : 0.0f;
    }

    // ---- Thread tile: 2 rows x 4 j (lanes = j-pairs).
    const int jg = t & 7;
    const int j0 = jg * 4;
    const int r0 = (t >> 3) * 2;

#pragma unroll
    for (int item = 0; item < ITEMS; ++item) {
        if (item == 0) { asm volatile("cp.async.wait_group 1;" ::: "memory"); }
        else           { asm volatile("cp.async.wait_group 0;" ::: "memory"); }
        __syncthreads();

        const float* xIs = xIb[item];
        const float* xJs = xJb[item];

        float2 a00 = {0.f,0.f}, a01 = {0.f,0.f}, a10 = {0.f,0.f}, a11 = {0.f,0.f};

        // Depth-1 prefetched mainloop: loads for i+1 issue before FMAs for i.
        float  p0 = xIs[r0 * XP];
        float  p1 = xIs[(r0 + 1) * XP];
        float4 pa = *reinterpret_cast<const float4*>(&As[j0]);
#pragma unroll
        for (int i = 0; i < TT; ++i) {
            const float  xv0 = p0;
            const float  xv1 = p1;
            const float4 av  = pa;
            if (i + 1 < TT) {
                p0 = xIs[ r0      * XP + i + 1];
                p1 = xIs[(r0 + 1) * XP + i + 1];
                pa = *reinterpret_cast<const float4*>(&As[(i + 1) * TT + j0]);
            }
            const float2 A01 = make_float2(av.x, av.y);
            const float2 A23 = make_float2(av.z, av.w);
            a00 = fma2(make_float2(xv0, xv0), A01, a00);
            a01 = fma2(make_float2(xv0, xv0), A23, a01);
            a10 = fma2(make_float2(xv1, xv1), A01, a10);
            a11 = fma2(make_float2(xv1, xv1), A23, a11);
        }

        const float4 xj0 = *reinterpret_cast<const float4*>(&xJs[ r0      * XP + j0]);
        const float4 xj1 = *reinterpret_cast<const float4*>(&xJs[(r0 + 1) * XP + j0]);
        float2 s0 = fma2(a00, make_float2(xj0.x, xj0.y),
                    fma2(a01, make_float2(xj0.z, xj0.w), make_float2(0.f, 0.f)));
        float2 s1 = fma2(a10, make_float2(xj1.x, xj1.y),
                    fma2(a11, make_float2(xj1.z, xj1.w), make_float2(0.f, 0.f)));
        float v0 = s0.x + s0.y;
        float v1 = s1.x + s1.y;

#pragma unroll
        for (int m = 4; m > 0; m >>= 1) {
            v0 += __shfl_xor_sync(0xffffffffu, v0, m, 32);
            v1 += __shfl_xor_sync(0xffffffffu, v1, m, 32);
        }
        if (jg == 0) {
            const int rb = rbase + item * ROWS;
            atomicAdd(&out[rb + r0],     v0);
            atomicAdd(&out[rb + r0 + 1], v1);
        }
    }
}

extern "C" void kernel_launch(void* const* d_in, const int* in_sizes, int n_in,
                              void* d_out, int out_size) {
    const float* x = (const float*)d_in[0];
    const float* w = (const float*)d_in[1];
    float* out = (float*)d_out;

    zero_out_kernel<<<4, 256>>>(out);                                   // tiny node
    quad_kernel<<<dim3(NPAIR, BATCH / (ROWS * ITEMS)), 256>>>(x, w, out);  // 288 blocks
}

// round 15
// speedup vs baseline: 1.3310x; 1.1138x over previous
#include <cuda_runtime.h>

#define DIM    256    // DIM_IN
#define BATCH  1024   // B
#define NI     32640  // C(256,2)

#define TT     32     // i/j tile size (8 tiles of 32)
#define ROWS   64     // batch rows per item
#define ITEMS  2      // y-items per block (fused in one mainloop)
#define NPAIR  36     // unordered tile pairs
#define XP     36     // x tile pitch in floats

__constant__ unsigned char cTI[NPAIR] = {0,0,0,0,0,0,0,0, 1,1,1,1,1,1,1, 2,2,2,2,2,2,
                                         3,3,3,3,3, 4,4,4,4, 5,5,5, 6,6, 7};
__constant__ unsigned char cTJ[NPAIR] = {0,1,2,3,4,5,6,7, 1,2,3,4,5,6,7, 2,3,4,5,6,7,
                                         3,4,5,6,7, 4,5,6,7, 5,6,7, 6,7, 7};

__global__ void zero_out_kernel(float* __restrict__ out) {
    out[blockIdx.x * 256 + threadIdx.x] = 0.0f;   // 4 blocks x 256
}

// Packed f32x2 FMA
__device__ __forceinline__ float2 fma2(float2 a, float2 b, float2 c) {
    float2 d;
    asm("fma.rn.f32x2 %0, %1, %2, %3;"
        : "=l"(*reinterpret_cast<unsigned long long*>(&d))
        : "l"(*reinterpret_cast<const unsigned long long*>(&a)),
          "l"(*reinterpret_cast<const unsigned long long*>(&b)),
          "l"(*reinterpret_cast<const unsigned long long*>(&c)));
    return d;
}

// 16B global->shared async copy (LDGSTS)
__device__ __forceinline__ void cp_async16(unsigned smem_addr, const void* gptr) {
    asm volatile("cp.async.ca.shared.global [%0], [%1], 16;"
                 :: "r"(smem_addr), "l"(__cvta_generic_to_global(gptr)) : "memory");
}

// out[b] = sum_{i<j} (w0+w1)*w0*w1 * x[b,i]*x[b,j]
// Block = one unordered tile pair x 2 FUSED 64-row items: one barrier, one
// mainloop with 8 FFMA2 (two independent accumulator sets) per shared A load.
__global__ void __launch_bounds__(256, 2)
quad_kernel(const float* __restrict__ x, const float* __restrict__ w,
            float* __restrict__ out) {
    __shared__ __align__(16) float As[TT * TT];                 // 4KB
    __shared__ __align__(16) float xIb[ITEMS][ROWS * XP];       // 2 x 9.2KB
    __shared__ __align__(16) float xJb[ITEMS][ROWS * XP];       // 2 x 9.2KB

    const int t     = threadIdx.x;
    const int pair  = blockIdx.x;
    const int ibase = cTI[pair] * TT;
    const int jbase = cTJ[pair] * TT;
    const int rbase = blockIdx.y * (ROWS * ITEMS);

    // ---- Issue BOTH items' x tiles via cp.async.
#pragma unroll
    for (int item = 0; item < ITEMS; ++item) {
        const unsigned sI = (unsigned)__cvta_generic_to_shared(xIb[item]);
        const unsigned sJ = (unsigned)__cvta_generic_to_shared(xJb[item]);
        const int rb = rbase + item * ROWS;
#pragma unroll
        for (int s = 0; s < 2; ++s) {
            const int c  = s * 256 + t;
            const int r  = c >> 3, cc = c & 7;       // 64 rows x 8 16B-chunks
            const long rowoff = (long)(rb + r) * DIM;
            cp_async16(sI + (r * XP + cc * 4) * 4, x + rowoff + ibase + cc * 4);
            cp_async16(sJ + (r * XP + cc * 4) * 4, x + rowoff + jbase + cc * 4);
        }
    }
    asm volatile("cp.async.commit_group;" ::: "memory");

    // ---- A tile (shared by both items): batched coalesced w loads, then STS.
    float w0v[4], w1v[4];
    bool  val[4];
#pragma unroll
    for (int s = 0; s < 4; ++s) {
        const int idx = s * 256 + t;
        const int gi = ibase + (idx >> 5);
        const int gj = jbase + (idx & 31);
        val[s] = (gj > gi);
        const int k = val[s] ? (gi * 255 - (gi * (gi - 1)) / 2 + (gj - gi - 1)) : 0;
        w0v[s] = __ldg(&w[k]);
        w1v[s] = __ldg(&w[NI + k]);
    }
#pragma unroll
    for (int s = 0; s < 4; ++s) {
        const int idx = s * 256 + t;
        As[idx] = val[s] ? (w0v[s] + w1v[s]) * w0v[s] * w1v[s] : 0.0f;
    }

    asm volatile("cp.async.wait_group 0;" ::: "memory");
    __syncthreads();   // the ONLY block barrier

    // ---- Thread tile: (2 rows x 2 items) x 4 j (lanes = j-pairs).
    const int jg = t & 7;
    const int j0 = jg * 4;
    const int r0 = (t >> 3) * 2;

    const float* xI0 = xIb[0] + r0 * XP;
    const float* xI1 = xIb[1] + r0 * XP;

    float2 b00 = {0.f,0.f}, b01 = {0.f,0.f}, b10 = {0.f,0.f}, b11 = {0.f,0.f};  // item 0
    float2 c00 = {0.f,0.f}, c01 = {0.f,0.f}, c10 = {0.f,0.f}, c11 = {0.f,0.f};  // item 1

#pragma unroll
    for (int i = 0; i < TT; ++i) {
        const float4 av = *reinterpret_cast<const float4*>(&As[i * TT + j0]);  // shared A
        const float u0 = xI0[i];
        const float u1 = xI0[XP + i];
        const float v0 = xI1[i];
        const float v1 = xI1[XP + i];
        const float2 A01 = make_float2(av.x, av.y);
        const float2 A23 = make_float2(av.z, av.w);
        b00 = fma2(make_float2(u0, u0), A01, b00);
        c00 = fma2(make_float2(v0, v0), A01, c00);
        b01 = fma2(make_float2(u0, u0), A23, b01);
        c01 = fma2(make_float2(v0, v0), A23, c01);
        b10 = fma2(make_float2(u1, u1), A01, b10);
        c10 = fma2(make_float2(v1, v1), A01, c10);
        b11 = fma2(make_float2(u1, u1), A23, b11);
        c11 = fma2(make_float2(v1, v1), A23, c11);
    }

    // ---- Epilogue: both items' dots with x_J, interleaved shuffle reduce.
    const float4 xj00 = *reinterpret_cast<const float4*>(&xJb[0][ r0      * XP + j0]);
    const float4 xj01 = *reinterpret_cast<const float4*>(&xJb[0][(r0 + 1) * XP + j0]);
    const float4 xj10 = *reinterpret_cast<const float4*>(&xJb[1][ r0      * XP + j0]);
    const float4 xj11 = *reinterpret_cast<const float4*>(&xJb[1][(r0 + 1) * XP + j0]);

    float2 sb0 = fma2(b00, make_float2(xj00.x, xj00.y),
                 fma2(b01, make_float2(xj00.z, xj00.w), make_float2(0.f, 0.f)));
    float2 sb1 = fma2(b10, make_float2(xj01.x, xj01.y),
                 fma2(b11, make_float2(xj01.z, xj01.w), make_float2(0.f, 0.f)));
    float2 sc0 = fma2(c00, make_float2(xj10.x, xj10.y),
                 fma2(c01, make_float2(xj10.z, xj10.w), make_float2(0.f, 0.f)));
    float2 sc1 = fma2(c10, make_float2(xj11.x, xj11.y),
                 fma2(c11, make_float2(xj11.z, xj11.w), make_float2(0.f, 0.f)));

    float vb0 = sb0.x + sb0.y, vb1 = sb1.x + sb1.y;
    float vc0 = sc0.x + sc0.y, vc1 = sc1.x + sc1.y;

#pragma unroll
    for (int m = 4; m > 0; m >>= 1) {   // reduce within 8-lane j-groups
        vb0 += __shfl_xor_sync(0xffffffffu, vb0, m, 32);
        vb1 += __shfl_xor_sync(0xffffffffu, vb1, m, 32);
        vc0 += __shfl_xor_sync(0xffffffffu, vc0, m, 32);
        vc1 += __shfl_xor_sync(0xffffffffu, vc1, m, 32);
    }
    if (jg == 0) {
        atomicAdd(&out[rbase + r0],            vb0);
        atomicAdd(&out[rbase + r0 + 1],        vb1);
        atomicAdd(&out[rbase + ROWS + r0],     vc0);
        atomicAdd(&out[rbase + ROWS + r0 + 1], vc1);
    }
}

extern "C" void kernel_launch(void* const* d_in, const int* in_sizes, int n_in,
                              void* d_out, int out_size) {
    const float* x = (const float*)d_in[0];
    const float* w = (const float*)d_in[1];
    float* out = (float*)d_out;

    zero_out_kernel<<<4, 256>>>(out);
    quad_kernel<<<dim3(NPAIR, BATCH / (ROWS * ITEMS)), 256>>>(x, w, out);  // 288 blocks
}